// round 14
// baseline (speedup 1.0000x reference)
#include <cuda_runtime.h>
#include <cstdint>

// Fully fused Precoding-GNN, R14: R13 base (proven 572us) with
//  - all weights pre-transposed ONCE to gmem (prep kernel);
//  - per-layer weight staging = float4 copies, double-buffered, issued INSIDE
//    the previous layer's FMA-bound edge phase (off the critical path);
//  - bias GEMM in f32x2 with broadcast wmT/wkT pair loads (256 vs 320 instr).
// Hot loops (edge GEMM, msgs, combine) byte-identical to R13.
// One sample per 2-CTA cluster, hidden state resident in SMEM all 5 layers.
// BS=1024, M=64, K=32, D=32. Each CTA owns 32 antennas -> 1024 edges.
// h layout: h[d][e], e = m_loc*32 + k (pitch 1024 floats).

#define NT 512
#define NW 16
#define TP 33  // transposed-table pitch: bank = (d + mk) % 32, conflict-free

typedef unsigned long long ull;

// Pre-transposed weights, 3072 floats per layer:
//  [l*3072 + 0   .. ] wsT[d*32+h]  (L5: packed [d*2+h])
//  [l*3072 + 1024.. ] wmT[d*32+h]  (L5: packed [d*2+h])
//  [l*3072 + 2048.. ] wkT[d*32+h]  (L5: packed [d*2+h])
__device__ __align__(16) float wTg[5 * 3072];

struct SM {
  float h[32 * 1024];      // 131072 B hidden state [d][e]
  float xs[2 * 1024];      //   8192 B layer-1 input [c][e]
  float wbuf[2][3072];     //  24576 B double-buffered {wsT, wmT, wkT}
  float mmT[32 * TP];      //   4224 B msg_m^T [d][m]
  float mkpT[2][32 * TP];  //   8448 B msg_k partial^T [d][k], parity buffered
  float mkcT[32 * TP];     //   4224 B msg_k combined^T [d][k]
  float bm[32 * 34];       //   4352 B Wm@msg_m  [m][h]
  float bk[32 * 34];       //   4352 B Wk@msg_k  [k][h]
  float red[NW];
  float powslot;
};

struct Params {
  const float* x;
  const float* w[15];
  float* out;
};

extern __shared__ __align__(16) char smem_raw[];

__device__ __forceinline__ uint32_t s2u(const void* p) {
  uint32_t a;
  asm("{ .reg .u64 t; cvta.to.shared.u64 t, %1; cvt.u32.u64 %0, t; }"
      : "=r"(a) : "l"(p));
  return a;
}
__device__ __forceinline__ float peer_ldf(const float* p, uint32_t peer) {
  uint32_t ra;
  asm("mapa.shared::cluster.u32 %0, %1, %2;" : "=r"(ra) : "r"(s2u(p)), "r"(peer));
  float v;
  asm volatile("ld.shared::cluster.f32 %0, [%1];" : "=f"(v) : "r"(ra));
  return v;
}
__device__ __forceinline__ void csync() {
  asm volatile("barrier.cluster.arrive.aligned;" ::: "memory");
  asm volatile("barrier.cluster.wait.aligned;" ::: "memory");
}
__device__ __forceinline__ ull pk2(float x, float y) {
  ull r; asm("mov.b64 %0,{%1,%2};" : "=l"(r) : "f"(x), "f"(y)); return r;
}
__device__ __forceinline__ void upk2(ull v, float& x, float& y) {
  asm("mov.b64 {%0,%1},%2;" : "=f"(x), "=f"(y) : "l"(v));
}
__device__ __forceinline__ void fma2(ull& d, ull a, ull b) {
  asm("fma.rn.f32x2 %0,%1,%2,%0;" : "+l"(d) : "l"(a), "l"(b));
}

// ---- prep: transpose all weights once into wTg ----
__global__ void prep_kernel(Params p) {
  int t = threadIdx.x;
  for (int i = t; i < 64; i += NT) {  // layer 1, DIN=2
    int d = i >> 5, hh = i & 31;
    wTg[d * 32 + hh] = p.w[0][hh * 2 + d];
    wTg[1024 + d * 32 + hh] = p.w[1][hh * 2 + d];
    wTg[2048 + d * 32 + hh] = p.w[2][hh * 2 + d];
  }
  for (int l = 1; l < 4; l++)  // layers 2-4, (32,32)
    for (int i = t; i < 1024; i += NT) {
      int d = i >> 5, hh = i & 31;
      wTg[l * 3072 + d * 32 + hh] = p.w[3 * l][hh * 32 + d];
      wTg[l * 3072 + 1024 + d * 32 + hh] = p.w[3 * l + 1][hh * 32 + d];
      wTg[l * 3072 + 2048 + d * 32 + hh] = p.w[3 * l + 2][hh * 32 + d];
    }
  for (int i = t; i < 64; i += NT) {  // layer 5, (2,32), packed stride-2
    int d = i >> 1, hh = i & 1;
    wTg[4 * 3072 + d * 2 + hh] = p.w[12][hh * 32 + d];
    wTg[4 * 3072 + 1024 + d * 2 + hh] = p.w[13][hh * 32 + d];
    wTg[4 * 3072 + 2048 + d * 2 + hh] = p.w[14][hh * 32 + d];
  }
}

// mmT[d][m] = sum_k src[d][m*32+k]  (contiguous float4 loads, 8-lane tree)
// mkpT[d][k] = sum_{m_loc} src[d][m*32+k]  (coalesced lanes, serial over m)
template <int DIN>
__device__ __forceinline__ void msgs(SM* s, const float* src, float* mkpT,
                                     int lane, int wid) {
  for (int r = wid; r < DIN * 8; r += NW) {
    int d = r >> 3, g = r & 7;  // g: group of 4 antennas (128 floats)
    float4 v = *(const float4*)(src + d * 1024 + g * 128 + lane * 4);
    float t = v.x + v.y + v.z + v.w;
    t += __shfl_xor_sync(0xffffffffu, t, 1);
    t += __shfl_xor_sync(0xffffffffu, t, 2);
    t += __shfl_xor_sync(0xffffffffu, t, 4);
    if ((lane & 7) == 0) s->mmT[d * TP + (g * 4 + (lane >> 3))] = t;
  }
  for (int d = wid; d < DIN; d += NW) {
    float t = 0.f;
#pragma unroll
    for (int m2 = 0; m2 < 32; m2++) t += src[d * 1024 + m2 * 32 + lane];
    mkpT[d * TP + lane] = t;  // coalesced, conflict-free
  }
}

// combine: mkcT = mkpT(local) + mkpT(peer); fully coalesced scalar
template <int DIN>
__device__ __forceinline__ void combine_mk(SM* s, const float* mkpT, int tid,
                                           uint32_t peer) {
  for (int i = tid; i < 32 * DIN; i += NT) {
    int d = i >> 5, k = i & 31;  // k = lane -> coalesced
    int off = d * TP + k;
    s->mkcT[off] = mkpT[off] + peer_ldf(mkpT + off, peer);
  }
}

// One GNN layer, DOUT=32, relu. src = xs (L1) or h (L2-4), dest = h in place.
// wb: this layer's staged weights {wsT, wmT, wkT}. During the edge phase the
// NEXT layer's weights are copied gmem->stage_dst (double buffer).
template <int DIN>
__device__ __forceinline__ void layer32(SM* s, const float* src,
                                        const float* wb, float* stage_dst,
                                        const float* stage_src, int par,
                                        int tid, int lane, int wid,
                                        uint32_t peer) {
  const float* wsT = wb;
  const float* wmT = wb + 1024;
  const float* wkT = wb + 2048;
  float* mkpT = s->mkpT[par];

  msgs<DIN>(s, src, mkpT, lane, wid);
  csync();  // mkpT visible cluster-wide; also orders local mmT
  combine_mk<DIN>(s, mkpT, tid, peer);
  __syncthreads();
  // bias GEMMs (f32x2): thread = (mk, h'-pair); tables conflict-free,
  // weight pairs warp-uniform LDS.64 broadcasts.
  {
    const int mk = tid & 31, hh2 = tid >> 5;  // hh2 in [0,16)
    ull tb = 0, tk = 0;
#pragma unroll
    for (int d = 0; d < DIN; d++) {
      float am = s->mmT[d * TP + mk];
      float ak = s->mkcT[d * TP + mk];
      ull wmv = *(const ull*)(wmT + d * 32 + 2 * hh2);
      ull wkv = *(const ull*)(wkT + d * 32 + 2 * hh2);
      fma2(tb, pk2(am, am), wmv);
      fma2(tk, pk2(ak, ak), wkv);
    }
    float a, b;
    upk2(tb, a, b); *(float2*)(s->bm + mk * 34 + 2 * hh2) = make_float2(a, b);
    upk2(tk, a, b); *(float2*)(s->bk + mk * 34 + 2 * hh2) = make_float2(a, b);
  }
  __syncthreads();

  // ---- stage next layer's weights (hidden under the FMA-bound edge loop) ----
  {
    const float4* srcv = (const float4*)stage_src;
    float4* dstv = (float4*)stage_dst;
    for (int i = tid; i < 768; i += NT) dstv[i] = srcv[i];
  }

  // ---- edge GEMM: 2 edges x 32 h' per thread (R3-exact) ----
  const int e0 = 2 * tid, m = e0 >> 5, k0 = e0 & 31;
  ull a0[16], a1[16];
#pragma unroll
  for (int j = 0; j < 16; j++) {
    float2 bmv = *(const float2*)(s->bm + m * 34 + 2 * j);
    float2 b0v = *(const float2*)(s->bk + k0 * 34 + 2 * j);
    float2 b1v = *(const float2*)(s->bk + (k0 + 1) * 34 + 2 * j);
    a0[j] = pk2(bmv.x + b0v.x, bmv.y + b0v.y);
    a1[j] = pk2(bmv.x + b1v.x, bmv.y + b1v.y);
  }
#pragma unroll 4
  for (int d = 0; d < DIN; d++) {
    float2 hv = *(const float2*)(src + d * 1024 + e0);
    ull H0 = pk2(hv.x, hv.x), H1 = pk2(hv.y, hv.y);
    const ulonglong2* wr = (const ulonglong2*)(wsT + d * 32);
#pragma unroll
    for (int q = 0; q < 8; q++) {
      ulonglong2 w = wr[q];  // broadcast LDS.128, used directly (no repack)
      fma2(a0[2 * q], H0, w.x);
      fma2(a0[2 * q + 1], H0, w.y);
      fma2(a1[2 * q], H1, w.x);
      fma2(a1[2 * q + 1], H1, w.y);
    }
  }
  // threads touch only their own 2 columns -> in-place is private, no barrier
#pragma unroll
  for (int j = 0; j < 16; j++) {
    float x0, x1, y0, y1;
    upk2(a0[j], x0, x1);
    upk2(a1[j], y0, y1);
    x0 = fmaxf(x0, 0.f); x1 = fmaxf(x1, 0.f);
    y0 = fmaxf(y0, 0.f); y1 = fmaxf(y1, 0.f);
    *(float2*)(s->h + (2 * j) * 1024 + e0) = make_float2(x0, y0);
    *(float2*)(s->h + (2 * j + 1) * 1024 + e0) = make_float2(x1, y1);
  }
  __syncthreads();  // h + staged weights ready for next layer
}

__global__ void __launch_bounds__(NT, 1) __cluster_dims__(2, 1, 1)
gnn_kernel(Params p) {
  SM* s = (SM*)smem_raw;
  const int tid = threadIdx.x, lane = tid & 31, wid = tid >> 5;
  uint32_t rank;
  asm("mov.u32 %0, %%cluster_ctarank;" : "=r"(rank));
  const uint32_t peer = rank ^ 1u;
  const int sample = blockIdx.x >> 1;

  // stage x -> xs[c][e], and layer-1 weights -> wbuf[0]
  {
    const float* xg = p.x + (size_t)sample * 4096 + (size_t)rank * 2048;
    float4 v = *(const float4*)(xg + 4 * tid);
    int e0 = 2 * tid;
    s->xs[e0] = v.x; s->xs[e0 + 1] = v.z;
    s->xs[1024 + e0] = v.y; s->xs[1024 + e0 + 1] = v.w;
    const float4* srcv = (const float4*)wTg;
    float4* dstv = (float4*)s->wbuf[0];
    for (int i = tid; i < 768; i += NT) dstv[i] = srcv[i];
  }
  __syncthreads();

  // parities: L1:0 L2:1 L3:0 L4:1 L5:0 (overwrite distance 2 => safe)
  // weight buffers: L1:0 L2:1 L3:0 L4:1 L5:0; each layer stages the next.
  layer32<2>(s, s->xs, s->wbuf[0], s->wbuf[1], wTg + 3072, 0, tid, lane, wid,
             peer);
  layer32<32>(s, s->h, s->wbuf[1], s->wbuf[0], wTg + 2 * 3072, 1, tid, lane,
              wid, peer);
  layer32<32>(s, s->h, s->wbuf[0], s->wbuf[1], wTg + 3 * 3072, 0, tid, lane,
              wid, peer);
  layer32<32>(s, s->h, s->wbuf[1], s->wbuf[0], wTg + 4 * 3072, 1, tid, lane,
              wid, peer);

  // ---- layer 5 (DIN=32, DOUT=2, no relu) + power norm + store ----
  {
    const float* wsT5 = s->wbuf[0];         // packed [d*2+h]
    const float* wmT5 = s->wbuf[0] + 1024;  // packed [d*2+h]
    const float* wkT5 = s->wbuf[0] + 2048;
    float* mkpT = s->mkpT[0];
    msgs<32>(s, s->h, mkpT, lane, wid);
    csync();
    combine_mk<32>(s, mkpT, tid, peer);
    __syncthreads();
    if (tid < 32) {  // bias: one mk per thread, both h' via f32x2
      ull tb = 0, tk = 0;
#pragma unroll
      for (int d = 0; d < 32; d++) {
        float am = s->mmT[d * TP + tid];
        float ak = s->mkcT[d * TP + tid];
        ull wmv = *(const ull*)(wmT5 + d * 2);
        ull wkv = *(const ull*)(wkT5 + d * 2);
        fma2(tb, pk2(am, am), wmv);
        fma2(tk, pk2(ak, ak), wkv);
      }
      float a, b;
      upk2(tb, a, b); *(float2*)(s->bm + tid * 34) = make_float2(a, b);
      upk2(tk, a, b); *(float2*)(s->bk + tid * 34) = make_float2(a, b);
    }
    __syncthreads();

    // 2 edges per thread
    const int e0 = 2 * tid, m = e0 >> 5, k0 = e0 & 31;
    float2 bmv = *(const float2*)(s->bm + m * 34);
    float2 b0v = *(const float2*)(s->bk + k0 * 34);
    float2 b1v = *(const float2*)(s->bk + (k0 + 1) * 34);
    ull a0 = pk2(bmv.x + b0v.x, bmv.y + b0v.y);
    ull a1 = pk2(bmv.x + b1v.x, bmv.y + b1v.y);
#pragma unroll 8
    for (int d = 0; d < 32; d++) {
      float2 hv = *(const float2*)(s->h + d * 1024 + e0);
      ull w = *(const ull*)(wsT5 + d * 2);
      fma2(a0, pk2(hv.x, hv.x), w);
      fma2(a1, pk2(hv.y, hv.y), w);
    }
    float x0, x1, y0, y1;
    upk2(a0, x0, x1);
    upk2(a1, y0, y1);

    // power = sum over whole sample of z^2
    float pl = x0 * x0 + x1 * x1 + y0 * y0 + y1 * y1;
    pl += __shfl_xor_sync(0xffffffffu, pl, 1);
    pl += __shfl_xor_sync(0xffffffffu, pl, 2);
    pl += __shfl_xor_sync(0xffffffffu, pl, 4);
    pl += __shfl_xor_sync(0xffffffffu, pl, 8);
    pl += __shfl_xor_sync(0xffffffffu, pl, 16);
    if (lane == 0) s->red[wid] = pl;
    __syncthreads();
    if (tid == 0) {
      float t = 0.f;
#pragma unroll
      for (int w2 = 0; w2 < NW; w2++) t += s->red[w2];
      s->powslot = t;
    }
    csync();  // both CTAs' powslot ready
    float al = rsqrtf(s->powslot + peer_ldf(&s->powslot, peer));  // PT = 1

    float4 o = make_float4(al * x0, al * x1, al * y0, al * y1);
    *(float4*)(p.out + (size_t)sample * 4096 + (size_t)rank * 2048 + 4 * tid) = o;
    csync();  // keep our smem alive until peer finished its powslot read
  }
}

extern "C" void kernel_launch(void* const* d_in, const int* in_sizes, int n_in,
                              void* d_out, int out_size) {
  Params p;
  p.x = (const float*)d_in[0];
  for (int i = 0; i < 15; i++) p.w[i] = (const float*)d_in[1 + i];
  p.out = (float*)d_out;

  prep_kernel<<<1, NT>>>(p);
  cudaFuncSetAttribute(gnn_kernel, cudaFuncAttributeMaxDynamicSharedMemorySize,
                       (int)sizeof(SM));
  gnn_kernel<<<2048, NT, sizeof(SM)>>>(p);
}